// round 9
// baseline (speedup 1.0000x reference)
#include <cuda_runtime.h>
#include <math.h>

#define BB 2
#define NN 384
#define CC 1024
#define HREPN 256
#define GHID 256
#define NHEADS 4
#define TOPKK 8
#define MAXDEG 400
#define NB 148

typedef unsigned long long ull;

// ---------------- scratch (device globals; no allocation allowed) ------------
__device__ __align__(16) float g_p1 [BB*NN*HREPN];
__device__ __align__(16) float g_p2 [BB*NN*HREPN];
__device__ __align__(16) float g_xw1[BB*NN*NHEADS*GHID];
__device__ float g_as1[BB*NN*NHEADS];
__device__ float g_ad1[BB*NN*NHEADS];
__device__ int   g_nbr[BB*NN*TOPKK];
__device__ int   g_srcl[BB*NN*MAXDEG];
__device__ int   g_deg [BB*NN];
__device__ float g_xw2[BB*NN*2];
__device__ float g_as2[BB*NN];
__device__ float g_ad2[BB*NN];
__device__ unsigned g_bar_cnt = 0;
__device__ unsigned g_bar_gen = 0;

// ---------------- f32x2 helpers ----------------------------------------------
__device__ __forceinline__ void ffma2(ull &d, ull a, ull b) {
    asm("fma.rn.f32x2 %0, %1, %2, %0;" : "+l"(d) : "l"(a), "l"(b));
}
__device__ __forceinline__ ull fma2v(ull a, ull b, ull c) {
    ull r; asm("fma.rn.f32x2 %0, %1, %2, %3;" : "=l"(r) : "l"(a), "l"(b), "l"(c)); return r;
}
__device__ __forceinline__ ull add2v(ull a, ull b) {
    ull r; asm("add.rn.f32x2 %0, %1, %2;" : "=l"(r) : "l"(a), "l"(b)); return r;
}
__device__ __forceinline__ ull pack2(float lo, float hi) {
    ull r; asm("mov.b64 %0, {%1, %2};" : "=l"(r) : "f"(lo), "f"(hi)); return r;
}
__device__ __forceinline__ void unpack2(ull v, float &lo, float &hi) {
    asm("mov.b64 {%0, %1}, %2;" : "=f"(lo), "=f"(hi) : "l"(v));
}
__device__ __forceinline__ float lo2(ull v) { return __uint_as_float((unsigned)(v & 0xffffffffull)); }
__device__ __forceinline__ float hi2(ull v) { return __uint_as_float((unsigned)(v >> 32)); }

// ---------------- grid-wide barrier (all NB blocks resident: 1 block/SM) -----
__device__ __forceinline__ void grid_bar() {
    __syncthreads();
    if (threadIdx.x == 0) {
        __threadfence();
        unsigned my = atomicAdd(&g_bar_gen, 0u);
        unsigned prev = atomicAdd(&g_bar_cnt, 1u);
        if (prev == NB - 1u) {
            g_bar_cnt = 0u;
            __threadfence();
            atomicAdd(&g_bar_gen, 1u);
        } else {
            while (atomicAdd(&g_bar_gen, 0u) == my) { __nanosleep(64); }
        }
        __threadfence();
    }
    __syncthreads();
}

// ============================ THE persistent kernel ==========================
__global__ __launch_bounds__(256, 1) void k_all(
    const float* __restrict__ feats,
    const float* __restrict__ boxes,
    const float* __restrict__ fc1_w,
    const float* __restrict__ fc1_b,
    const float* __restrict__ fc2_w,
    const float* __restrict__ gat1_w,
    const float* __restrict__ att_src,
    const float* __restrict__ att_dst,
    const float* __restrict__ gat1_b,
    const float* __restrict__ gat2_w,
    const float* __restrict__ att_src2,
    const float* __restrict__ att_dst2,
    const float* __restrict__ gat2_b,
    float* __restrict__ out)
{
    __shared__ __align__(16) float sm[15616];   // 62.4KB union (gemm is max)
    int tid = threadIdx.x;
    int bid0 = blockIdx.x;
    int warp = tid >> 5, lane = tid & 31;

    // ================= PHASE 1: GEMMs (144 tasks, 1 per block) ==============
    if (bid0 < 144) {
        int bidt = bid0;
        int sel, b, by, bx;
        if (bidt < 48) { sel = 0; b = bidt / 24; int r = bidt % 24; by = r / 8;  bx = r % 8;  }
        else { sel = 1; int r = bidt - 48; b = r / 48; r %= 48;     by = r / 16; bx = r % 16; }

        int row0 = by * 128, col0 = bx * 64;
        const float* A = feats + b*NN*CC;
        const float* Bm; float* Cm;
        int ldb, Nc, dcol0;
        float* Wg4 = sm + 15360;
        if (sel == 0) {
            ldb = 256; Nc = 256;
            if (col0 < 256) { Bm = fc1_w;            Cm = g_p1 + b*NN*256; dcol0 = col0; }
            else            { Bm = fc1_w + 1024*256; Cm = g_p2 + b*NN*256; dcol0 = col0 - 256; }
        } else {
            ldb = 1024; Nc = 1024; Bm = gat1_w; Cm = g_xw1 + b*NN*1024; dcol0 = col0;
            Wg4[tid] = gat1_w[(1024 + (tid >> 6))*1024 + col0 + (tid & 63)];
        }

        int khalf = tid >> 7, htid = tid & 127;
        int tx = htid & 7, ty = htid >> 3;
        #define ASM(kh,bf) (sm + ((kh)*2+(bf))*2560)
        #define BSM(kh,bf) (sm + 10240 + ((kh)*2+(bf))*1280)

        ull acc[8][8];
        #pragma unroll
        for (int r = 0; r < 8; r++)
            #pragma unroll
            for (int j = 0; j < 8; j++) acc[r][j] = 0ull;

        int arow = htid >> 2, aslot = htid & 3;
        int bc = htid & 63, bk = htid >> 6;
        int kbase = khalf * 512;
        const float* ApB = A + (row0 + arow)*1024 + kbase + aslot*4;
        const float* Bp  = Bm + (ull)kbase*ldb + dcol0 + bc;

        float4 pa[4]; float pb[8];
        #pragma unroll
        for (int m = 0; m < 4; m++) pa[m] = *(const float4*)(ApB + m*32*1024);
        #pragma unroll
        for (int m = 0; m < 8; m++) pb[m] = Bp[(bk*8 + m)*ldb];
        #pragma unroll
        for (int m = 0; m < 4; m++) *(float4*)&ASM(khalf,0)[(arow + 32*m)*20 + aslot*4] = pa[m];
        #pragma unroll
        for (int m = 0; m < 8; m++) BSM(khalf,0)[bc*20 + bk*8 + m] = pb[m];
        __syncthreads();

        for (int t = 0; t < 32; t++) {
            int cur = t & 1, nxt = cur ^ 1;
            if (t < 31) {
                int k0 = (t + 1) * 16;
                #pragma unroll
                for (int m = 0; m < 4; m++) pa[m] = *(const float4*)(ApB + m*32*1024 + k0);
                #pragma unroll
                for (int m = 0; m < 8; m++) pb[m] = Bp[(k0 + bk*8 + m)*ldb];
            }
            #pragma unroll
            for (int kp = 0; kp < 8; kp++) {
                ull av[8], bv[8];
                #pragma unroll
                for (int r = 0; r < 8; r++)
                    av[r] = *(const ull*)&ASM(khalf,cur)[(ty + 16*r)*20 + 2*kp];
                #pragma unroll
                for (int j = 0; j < 8; j++)
                    bv[j] = *(const ull*)&BSM(khalf,cur)[(tx + 8*j)*20 + 2*kp];
                #pragma unroll
                for (int r = 0; r < 8; r++)
                    #pragma unroll
                    for (int j = 0; j < 8; j++) ffma2(acc[r][j], av[r], bv[j]);
            }
            if (t < 31) {
                #pragma unroll
                for (int m = 0; m < 4; m++) *(float4*)&ASM(khalf,nxt)[(arow + 32*m)*20 + aslot*4] = pa[m];
                #pragma unroll
                for (int m = 0; m < 8; m++) BSM(khalf,nxt)[bc*20 + bk*8 + m] = pb[m];
            }
            __syncthreads();
        }

        // combine K-halves via padded smem (aliases As region — dead now)
        float* comb = sm;
        if (khalf == 1) {
            #pragma unroll
            for (int r = 0; r < 8; r++)
                #pragma unroll
                for (int j = 0; j < 8; j++)
                    comb[htid*65 + r*8 + j] = lo2(acc[r][j]) + hi2(acc[r][j]);
        }
        __syncthreads();
        if (khalf == 0) {
            #pragma unroll
            for (int r = 0; r < 8; r++) {
                int row = row0 + ty + 16*r;
                float g0 = 0.f, g1 = 0.f, g2 = 0.f, g3 = 0.f;
                if (sel == 1) {
                    const float* bx4 = boxes + (b*NN + row)*4;
                    float x0 = bx4[0]*(1.0f/800.0f), y0 = bx4[1]*(1.0f/800.0f);
                    float x1 = bx4[2]*(1.0f/800.0f), y1 = bx4[3]*(1.0f/800.0f);
                    g0 = x0; g1 = y0; g2 = x1 - x0; g3 = y1 - y0;
                }
                #pragma unroll
                for (int j = 0; j < 8; j++) {
                    int c = tx + 8*j;
                    float s = (lo2(acc[r][j]) + hi2(acc[r][j])) + comb[htid*65 + r*8 + j];
                    if (sel == 1) {
                        s = fmaf(g0, Wg4[0*64 + c], s);
                        s = fmaf(g1, Wg4[1*64 + c], s);
                        s = fmaf(g2, Wg4[2*64 + c], s);
                        s = fmaf(g3, Wg4[3*64 + c], s);
                    }
                    Cm[row*Nc + dcol0 + c] = s;
                }
            }
        }
    }
    grid_bar();

    // ========== PHASE 2: rel+topk (tasks 0..191) | asad (192..575) ==========
    for (int task = bid0; task < 576; task += NB) {
        __syncthreads();
        if (task >= 192) {
            int bn = (task - 192)*2 + (tid >> 7);
            int h = (tid >> 5) & 3;
            const float* xw = g_xw1 + bn*1024 + h*256 + lane*8;
            float4 v0 = *(const float4*)xw;
            float4 v1 = *(const float4*)(xw + 4);
            const float* asr = att_src + h*256 + lane*8;
            const float* adr = att_dst + h*256 + lane*8;
            float4 s0 = *(const float4*)asr;
            float4 s1 = *(const float4*)(asr + 4);
            float4 d0 = *(const float4*)adr;
            float4 d1 = *(const float4*)(adr + 4);
            float ss = v0.x*s0.x + v0.y*s0.y + v0.z*s0.z + v0.w*s0.w
                     + v1.x*s1.x + v1.y*s1.y + v1.z*s1.z + v1.w*s1.w;
            float dd = v0.x*d0.x + v0.y*d0.y + v0.z*d0.z + v0.w*d0.w
                     + v1.x*d1.x + v1.y*d1.y + v1.z*d1.z + v1.w*d1.w;
            #pragma unroll
            for (int o = 16; o; o >>= 1) {
                ss += __shfl_down_sync(0xffffffffu, ss, o);
                dd += __shfl_down_sync(0xffffffffu, dd, o);
            }
            if (lane == 0) { g_as1[bn*4 + h] = ss; g_ad1[bn*4 + h] = dd; }
            continue;
        }

        int b = task / 96, igrp = task % 96;
        int i0 = igrp * 4;
        float* srow = sm;            // [4][NN]
        float* sbx  = sm + 1536;     // [16]

        if (tid < 16) sbx[tid] = boxes[(b*NN + i0 + (tid >> 2))*4 + (tid & 3)];

        ull wg2[4][4], sp1q[4][4];
        float w2lo[4], w2hi[4];
        #pragma unroll
        for (int p = 0; p < 4; p++) {
            int k0 = lane + 64*p, k1 = k0 + 32;
            w2lo[p] = fc2_w[k0];
            w2hi[p] = fc2_w[k1];
            #pragma unroll
            for (int d = 0; d < 4; d++)
                wg2[d][p] = pack2(fc1_w[(2048+d)*256 + k0], fc1_w[(2048+d)*256 + k1]);
            float b0 = fc1_b[k0], b1 = fc1_b[k1];
            #pragma unroll
            for (int q = 0; q < 4; q++) {
                const float* p1r = g_p1 + (b*NN + i0 + q)*256;
                sp1q[q][p] = pack2(p1r[k0] + b0, p1r[k1] + b1);
            }
        }
        __syncthreads();

        const float* p2b = g_p2 + b*NN*256;
        const float* bxb = boxes + b*NN*4;

        for (int j = warp; j < NN; j += 8) {
            float4 bj = *(const float4*)&bxb[j*4];
            ull p2v[4];
            #pragma unroll
            for (int p = 0; p < 4; p++) {
                int k0 = lane + 64*p;
                p2v[p] = pack2(p2b[j*256 + k0], p2b[j*256 + k0 + 32]);
            }
            #pragma unroll
            for (int q = 0; q < 4; q++) {
                float d0 = fabsf(sbx[q*4+0] - bj.x);
                float d1 = fabsf(sbx[q*4+1] - bj.y);
                float d2 = fabsf(sbx[q*4+2] - bj.z);
                float d3 = fabsf(sbx[q*4+3] - bj.w);
                ull a0 = pack2(d0, d0), a1 = pack2(d1, d1);
                ull a2 = pack2(d2, d2), a3 = pack2(d3, d3);
                float sum = 0.f;
                #pragma unroll
                for (int p = 0; p < 4; p++) {
                    ull t2 = add2v(sp1q[q][p], p2v[p]);
                    t2 = fma2v(a0, wg2[0][p], t2);
                    t2 = fma2v(a1, wg2[1][p], t2);
                    t2 = fma2v(a2, wg2[2][p], t2);
                    t2 = fma2v(a3, wg2[3][p], t2);
                    float tl, th;
                    unpack2(t2, tl, th);
                    tl = fmaxf(tl, 0.f);
                    th = fmaxf(th, 0.f);
                    sum = fmaf(tl, w2lo[p], sum);
                    sum = fmaf(th, w2hi[p], sum);
                }
                #pragma unroll
                for (int o = 16; o; o >>= 1) sum += __shfl_down_sync(0xffffffffu, sum, o);
                if (lane == 0)
                    srow[q*NN + j] = sum - ((j == i0 + q) ? 1e6f : 0.f);
            }
        }
        __syncthreads();

        if (warp < 4) {
            int q = warp, i = i0 + q;
            for (int sel2 = 0; sel2 < TOPKK; sel2++) {
                float bv = -3.4e38f; int bi = 1 << 30;
                for (int j = lane; j < NN; j += 32) {
                    float v = srow[q*NN + j];
                    if (v > bv || (v == bv && j < bi)) { bv = v; bi = j; }
                }
                #pragma unroll
                for (int o = 16; o; o >>= 1) {
                    float ov = __shfl_xor_sync(0xffffffffu, bv, o);
                    int   oi = __shfl_xor_sync(0xffffffffu, bi, o);
                    if (ov > bv || (ov == bv && oi < bi)) { bv = ov; bi = oi; }
                }
                if (lane == 0) {
                    g_nbr[(b*NN + i)*TOPKK + sel2] = bi;
                    srow[q*NN + bi] = -3.4e38f;
                }
                __syncwarp();
            }
        }
    }
    grid_bar();

    // ========== PHASE 3: GAT1 fused build+softmax+aggregate+xw2 (768) =======
    for (int task = bid0; task < 768; task += NB) {
        __syncthreads();
        int bn = task; int b = bn / NN, tt = bn % NN;
        int*   ssrc = (int*)sm;            // 400
        float* sal  = sm + 400;            // 4*400
        float* sas1 = sm + 2000;           // 1536
        int*   scnt = (int*)(sm + 3536);   // 256
        float* red  = sm + 3792;           // 16
        int*   sdeg = (int*)(sm + 3808);

        #pragma unroll
        for (int it = 0; it < 6; it++)
            sas1[tid + it*256] = g_as1[b*NN*4 + tid + it*256];

        const int* nb = g_nbr + b*NN*TOPKK;
        int myc0 = 0, myc1 = 0;
        int ia = 2*tid, ib = 2*tid + 1;
        if (tid < 192) {
            #pragma unroll
            for (int k = 0; k < TOPKK; k++) {
                myc0 += (nb[ia*TOPKK + k] == tt);
                myc1 += (nb[ib*TOPKK + k] == tt);
            }
        }
        int tot = myc0 + myc1;
        scnt[tid] = tot;
        __syncthreads();
        for (int s = 1; s < 256; s <<= 1) {
            int v = (tid >= s) ? scnt[tid - s] : 0;
            __syncthreads();
            scnt[tid] += v;
            __syncthreads();
        }
        int off = scnt[tid] - tot;
        int* dst = g_srcl + bn*MAXDEG;
        if (tid < 192) {
            if (myc0) {
                #pragma unroll
                for (int k = 0; k < TOPKK; k++)
                    if (nb[ia*TOPKK + k] == tt) { ssrc[off] = ia; dst[off] = ia; off++; }
            }
            if (myc1) {
                #pragma unroll
                for (int k = 0; k < TOPKK; k++)
                    if (nb[ib*TOPKK + k] == tt) { ssrc[off] = ib; dst[off] = ib; off++; }
            }
        }
        if (tid == 255) {
            int total = scnt[255];
            ssrc[total] = tt;
            dst[total] = tt;
            g_deg[bn] = total + 1;
            *sdeg = total + 1;
        }
        __syncthreads();
        int deg = *sdeg;

        if (warp < NHEADS) {
            int h = warp;
            float adv = g_ad1[bn*4 + h];
            float m = -3.4e38f;
            for (int s = lane; s < deg; s += 32) {
                float e = sas1[ssrc[s]*4 + h] + adv;
                e = (e >= 0.f) ? e : 0.2f*e;
                sal[h*MAXDEG + s] = e;
                m = fmaxf(m, e);
            }
            #pragma unroll
            for (int o = 16; o; o >>= 1) m = fmaxf(m, __shfl_xor_sync(0xffffffffu, m, o));
            float sum = 0.f;
            for (int s = lane; s < deg; s += 32) {
                float ex = expf(sal[h*MAXDEG + s] - m);
                sal[h*MAXDEG + s] = ex;
                sum += ex;
            }
            #pragma unroll
            for (int o = 16; o; o >>= 1) sum += __shfl_xor_sync(0xffffffffu, sum, o);
            float inv = 1.f / fmaxf(sum, 1e-16f);
            for (int s = lane; s < deg; s += 32) sal[h*MAXDEG + s] *= inv;
        }
        __syncthreads();

        const float* xwb = g_xw1 + b*NN*1024;
        const float* salh = sal + (tid >> 6)*MAXDEG;
        float4 acc0 = make_float4(0.f, 0.f, 0.f, 0.f);
        float4 acc1 = make_float4(0.f, 0.f, 0.f, 0.f);
        int col4 = tid * 4;
        int s = 0;
        for (; s + 1 < deg; s += 2) {
            float4 v0 = *(const float4*)&xwb[ssrc[s  ]*1024 + col4];
            float4 v1 = *(const float4*)&xwb[ssrc[s+1]*1024 + col4];
            float a0 = salh[s], a1 = salh[s+1];
            acc0.x = fmaf(v0.x, a0, acc0.x); acc0.y = fmaf(v0.y, a0, acc0.y);
            acc0.z = fmaf(v0.z, a0, acc0.z); acc0.w = fmaf(v0.w, a0, acc0.w);
            acc1.x = fmaf(v1.x, a1, acc1.x); acc1.y = fmaf(v1.y, a1, acc1.y);
            acc1.z = fmaf(v1.z, a1, acc1.z); acc1.w = fmaf(v1.w, a1, acc1.w);
        }
        if (s < deg) {
            float4 v0 = *(const float4*)&xwb[ssrc[s]*1024 + col4];
            float a0 = salh[s];
            acc0.x = fmaf(v0.x, a0, acc0.x); acc0.y = fmaf(v0.y, a0, acc0.y);
            acc0.z = fmaf(v0.z, a0, acc0.z); acc0.w = fmaf(v0.w, a0, acc0.w);
        }
        float4 bia = *(const float4*)&gat1_b[col4];
        float4 oh;
        oh.x = fmaxf(acc0.x + acc1.x + bia.x, 0.f);
        oh.y = fmaxf(acc0.y + acc1.y + bia.y, 0.f);
        oh.z = fmaxf(acc0.z + acc1.z + bia.z, 0.f);
        oh.w = fmaxf(acc0.w + acc1.w + bia.w, 0.f);

        float4 w0 = *(const float4*)&gat2_w[col4*2];
        float4 w1 = *(const float4*)&gat2_w[col4*2 + 4];
        float c0 = oh.x*w0.x + oh.y*w0.z + oh.z*w1.x + oh.w*w1.z;
        float c1 = oh.x*w0.y + oh.y*w0.w + oh.z*w1.y + oh.w*w1.w;
        #pragma unroll
        for (int o = 16; o; o >>= 1) {
            c0 += __shfl_down_sync(0xffffffffu, c0, o);
            c1 += __shfl_down_sync(0xffffffffu, c1, o);
        }
        if (lane == 0) { red[warp*2 + 0] = c0; red[warp*2 + 1] = c1; }
        __syncthreads();
        if (tid == 0) {
            float s0 = 0.f, s1 = 0.f;
            #pragma unroll
            for (int w = 0; w < 8; w++) { s0 += red[w*2]; s1 += red[w*2 + 1]; }
            g_xw2[bn*2 + 0] = s0;
            g_xw2[bn*2 + 1] = s1;
            g_as2[bn] = s0*att_src2[0] + s1*att_src2[1];
            g_ad2[bn] = s0*att_dst2[0] + s1*att_dst2[1];
        }
    }
    grid_bar();

    // ========== PHASE 4: GAT2 (96 tasks, 8 nodes each) ======================
    if (bid0 < 96) {
        float* s_as2 = sm;                  // 384
        float* s_xw2 = sm + 384;            // 768
        float* sal2  = sm + 1152;           // 8*400
        int*   ssrc2 = (int*)(sm + 4352);   // 8*400
        int n0 = bid0 * 8;
        int b = n0 / NN;

        for (int i = tid; i < NN; i += 256)   s_as2[i] = g_as2[b*NN + i];
        for (int i = tid; i < NN*2; i += 256) s_xw2[i] = g_xw2[b*NN*2 + i];
        __syncthreads();

        int bn = n0 + warp;
        int deg = g_deg[bn];
        float* salw = sal2 + warp*MAXDEG;
        int*   srcw = ssrc2 + warp*MAXDEG;
        for (int s = lane; s < deg; s += 32) srcw[s] = g_srcl[bn*MAXDEG + s];
        __syncwarp();
        float adv = g_ad2[bn];
        float m = -3.4e38f;
        for (int s = lane; s < deg; s += 32) {
            float e = s_as2[srcw[s]] + adv;
            e = (e >= 0.f) ? e : 0.2f*e;
            salw[s] = e;
            m = fmaxf(m, e);
        }
        #pragma unroll
        for (int o = 16; o; o >>= 1) m = fmaxf(m, __shfl_xor_sync(0xffffffffu, m, o));
        float sum = 0.f;
        for (int s = lane; s < deg; s += 32) {
            float ex = expf(salw[s] - m);
            salw[s] = ex;
            sum += ex;
        }
        #pragma unroll
        for (int o = 16; o; o >>= 1) sum += __shfl_xor_sync(0xffffffffu, sum, o);
        float inv = 1.f / fmaxf(sum, 1e-16f);
        __syncwarp();
        float a0 = 0.f, a1 = 0.f;
        for (int s = lane; s < deg; s += 32) {
            float w = salw[s] * inv;
            int sc = srcw[s];
            a0 = fmaf(s_xw2[sc*2 + 0], w, a0);
            a1 = fmaf(s_xw2[sc*2 + 1], w, a1);
        }
        #pragma unroll
        for (int o = 16; o; o >>= 1) {
            a0 += __shfl_down_sync(0xffffffffu, a0, o);
            a1 += __shfl_down_sync(0xffffffffu, a1, o);
        }
        if (lane == 0) {
            out[bn*2 + 0] = a0 + gat2_b[0];
            out[bn*2 + 1] = a1 + gat2_b[1];
        }
    }
}

// ---------------- launch ------------------------------------------------------
extern "C" void kernel_launch(void* const* d_in, const int* in_sizes, int n_in,
                              void* d_out, int out_size)
{
    const float* feats   = (const float*)d_in[0];
    const float* boxes   = (const float*)d_in[1];
    const float* fc1_w   = (const float*)d_in[2];
    const float* fc1_b   = (const float*)d_in[3];
    const float* fc2_w   = (const float*)d_in[4];
    // d_in[5] = fc2_b : constant shift, irrelevant for top-k
    const float* gat1_w  = (const float*)d_in[6];
    const float* g1as    = (const float*)d_in[7];
    const float* g1ad    = (const float*)d_in[8];
    const float* gat1_b  = (const float*)d_in[9];
    const float* gat2_w  = (const float*)d_in[10];
    const float* g2as    = (const float*)d_in[11];
    const float* g2ad    = (const float*)d_in[12];
    const float* gat2_b  = (const float*)d_in[13];
    float* out = (float*)d_out;

    k_all<<<NB, 256>>>(feats, boxes, fc1_w, fc1_b, fc2_w, gat1_w,
                       g1as, g1ad, gat1_b, gat2_w, g2as, g2ad, gat2_b, out);
    (void)in_sizes; (void)n_in; (void)out_size;
}